// round 4
// baseline (speedup 1.0000x reference)
#include <cuda_runtime.h>
#include <cstdint>

// ---------------------------------------------------------------------------
// OfflineSlidingWindowAttn  (B=2, SQ=SK=2048, HQ=32, HKV=8, D=128, W=512,
// causal, cap=30 tanh, softmax-clip clamp(1.02p-0.01,0,1))
//
// Two-pass per 64-query tile (clip needs the full row sum before weighting):
//   pass 1: QK tf32-mma -> cap -> mask -> exp -> store E tile in smem, row sums
//   pass 2: p = clamp(1.02*e/l - 0.01, 0, 1) -> PV tf32-mma -> store O
//
// R1: Q-fragment register hoist; poly-tanh fast path; tile-level full flag.
// R2: software-pipelined K/V global loads (register prefetch of tile t+1
//     overlapped with MMA of tile t; V tile 0 prefetched under the row-sum).
// R3: audited/frozen baseline; constant folding in epilogues.
// Known risk: plain tf32 rel-err budget ~7-9e-4 (gate 1e-3). If the first
// real bench fails on rel_err, switch QK to 3xTF32 compensation.
// ---------------------------------------------------------------------------

#define HEAD_DIM   128
#define NUM_Q_HEAD 32
#define NUM_KV_HEAD 8
#define GQA_GROUPS (NUM_Q_HEAD / NUM_KV_HEAD)
#define WINDOW     512
#define BQ         64
#define BK         64
#define NTHREADS   256

#define QPITCH 132   // floats; 132 % 32 == 4  -> bank = (4*row + col) % 32
#define KPITCH 132
#define VPITCH 136   // 136 % 32 == 8  -> bank = (8*k + n) % 32
#define EPITCH 580   // 580 % 32 == 4

#define SCALE_QK 0.08838834764831845f          // 1/sqrt(128)
#define CAPV     30.0f
#define SCALE_Y  (SCALE_QK / CAPV)             // folded: y = acc * SCALE_Y

// per-thread prefetch: BK*HEAD_DIM/4 float4 / NTHREADS = 8
#define PF_ITERS ((BK * HEAD_DIM / 4) / NTHREADS)

// smem layout (bytes)
#define SM_Q_OFF   0
#define SM_Q_BYTES (BQ * QPITCH * 4)                 // 33792
#define SM_KV_OFF  (SM_Q_OFF + SM_Q_BYTES)
#define SM_KV_BYTES (BK * VPITCH * 4)                // 34816 (K uses pitch 132 inside)
#define SM_E_OFF   (SM_KV_OFF + SM_KV_BYTES)
#define SM_E_BYTES (BQ * EPITCH * 4)                 // 148480
#define SM_L_OFF   (SM_E_OFF + SM_E_BYTES)
#define SM_L_BYTES (BQ * 4)
#define SM_TOTAL   (SM_L_OFF + SM_L_BYTES)           // 217600

__device__ __forceinline__ uint32_t f2tf32(float f) {
    uint32_t u;
    asm("cvt.rna.tf32.f32 %0, %1;" : "=r"(u) : "f"(f));
    return u;
}

__device__ __forceinline__ void mma_tf32(float c[4],
                                         uint32_t a0, uint32_t a1, uint32_t a2, uint32_t a3,
                                         uint32_t b0, uint32_t b1) {
    asm volatile(
        "mma.sync.aligned.m16n8k8.row.col.f32.tf32.tf32.f32 "
        "{%0,%1,%2,%3}, {%4,%5,%6,%7}, {%8,%9}, {%0,%1,%2,%3};"
        : "+f"(c[0]), "+f"(c[1]), "+f"(c[2]), "+f"(c[3])
        : "r"(a0), "r"(a1), "r"(a2), "r"(a3), "r"(b0), "r"(b1));
}

// issue the 8 per-thread LDG.128 for one 64x128 K/V tile
__device__ __forceinline__ void tile_ldg(float4 pf[PF_ITERS],
                                         const float* __restrict__ base,
                                         int kt, size_t row_stride, int tid) {
#pragma unroll
    for (int it = 0; it < PF_ITERS; ++it) {
        int idx = tid + it * NTHREADS;
        int r = idx >> 5;
        int c = (idx & 31) << 2;
        pf[it] = *reinterpret_cast<const float4*>(base + (size_t)(kt + r) * row_stride + c);
    }
}

// convert + store a prefetched tile into smem at the given pitch
__device__ __forceinline__ void tile_sts(const float4 pf[PF_ITERS],
                                         uint32_t* __restrict__ dst,
                                         int pitch, int tid) {
#pragma unroll
    for (int it = 0; it < PF_ITERS; ++it) {
        int idx = tid + it * NTHREADS;
        int r = idx >> 5;
        int c = (idx & 31) << 2;
        uint4 u;
        u.x = f2tf32(pf[it].x); u.y = f2tf32(pf[it].y);
        u.z = f2tf32(pf[it].z); u.w = f2tf32(pf[it].w);
        *reinterpret_cast<uint4*>(dst + r * pitch + c) = u;
    }
}

__global__ __launch_bounds__(NTHREADS, 1)
void swa_kernel(const float* __restrict__ q,
                const float* __restrict__ k,
                const float* __restrict__ v,
                float* __restrict__ out,
                int SQ) {
    extern __shared__ char smem[];
    uint32_t* Qs = reinterpret_cast<uint32_t*>(smem + SM_Q_OFF);
    uint32_t* KVs = reinterpret_cast<uint32_t*>(smem + SM_KV_OFF);
    float*    Es = reinterpret_cast<float*>(smem + SM_E_OFF);
    float*    Ls = reinterpret_cast<float*>(smem + SM_L_OFF);

    const int qt = blockIdx.x;
    const int h  = blockIdx.y;
    const int b  = blockIdx.z;
    const int kvh = h / GQA_GROUPS;
    const int qs = qt * BQ;

    const int tid  = threadIdx.x;
    const int warp = tid >> 5;
    const int lane = tid & 31;
    const int g = lane >> 2;   // group id 0..7
    const int m = lane & 3;    // 0..3

    const size_t q_row_stride  = (size_t)NUM_Q_HEAD * HEAD_DIM;   // 4096
    const size_t kv_row_stride = (size_t)NUM_KV_HEAD * HEAD_DIM;  // 1024

    const float* qbase = q + (((size_t)b * SQ + qs) * NUM_Q_HEAD + h) * HEAD_DIM;
    const float* kbase = k + ((size_t)b * SQ * NUM_KV_HEAD + kvh) * HEAD_DIM;
    const float* vbase = v + ((size_t)b * SQ * NUM_KV_HEAD + kvh) * HEAD_DIM;

    // ---- key tile range ----
    int wstart = qs - WINDOW; if (wstart < 0) wstart = 0;
    const int kstart = wstart & ~(BK - 1);
    const int klast  = (qs + BQ - 1) & ~(BK - 1);
    const int ntiles = (klast - kstart) / BK + 1;   // <= 9

    // ---- prefetch K tile 0, then load Q tile (overlaps with K LDG) ----
    float4 pf[PF_ITERS];
    tile_ldg(pf, kbase, kstart, kv_row_stride, tid);

#pragma unroll
    for (int it = 0; it < (BQ * HEAD_DIM / 4) / NTHREADS; ++it) {
        int idx = tid + it * NTHREADS;       // float4 index
        int r = idx >> 5;                    // 32 float4 per row
        int c = (idx & 31) << 2;             // float col
        float4 f = *reinterpret_cast<const float4*>(qbase + (size_t)r * q_row_stride + c);
        uint4 u;
        u.x = f2tf32(f.x); u.y = f2tf32(f.y); u.z = f2tf32(f.z); u.w = f2tf32(f.w);
        *reinterpret_cast<uint4*>(Qs + r * QPITCH + c) = u;
    }

    // warp tiling for pass 1
    const int rw = (warp & 3) * 16;   // S row block
    const int cb = (warp >> 2) * 32;  // S col block (4 n-tiles of 8)

    __syncthreads();   // Q tile visible to all warps

    // ---- hoist Q mma fragments to registers (read smem once, not per tile) ----
    uint32_t qa[16][4];
    {
        const uint32_t* qrow0 = Qs + (rw + g) * QPITCH;
        const uint32_t* qrow1 = Qs + (rw + g + 8) * QPITCH;
#pragma unroll
        for (int ks = 0; ks < 16; ++ks) {
            const int kk = ks * 8;
            qa[ks][0] = qrow0[kk + m];
            qa[ks][1] = qrow1[kk + m];
            qa[ks][2] = qrow0[kk + m + 4];
            qa[ks][3] = qrow1[kk + m + 4];
        }
    }

    // ================= PASS 1: E = exp(cap(QK)) with mask =================
    for (int t = 0; t < ntiles; ++t) {
        const int kt = kstart + t * BK;
        __syncthreads();                 // prev tile's consumers done
        tile_sts(pf, KVs, KPITCH, tid);  // K tile t -> smem
        __syncthreads();
        if (t + 1 < ntiles)              // overlap tile t+1 LDG with MMA of t
            tile_ldg(pf, kbase, kt + BK, kv_row_stride, tid);

        float acc[4][4];
#pragma unroll
        for (int nt = 0; nt < 4; ++nt)
#pragma unroll
            for (int e = 0; e < 4; ++e) acc[nt][e] = 0.0f;

#pragma unroll 4
        for (int ks = 0; ks < 16; ++ks) {
            const int kk = ks * 8;
#pragma unroll
            for (int nt = 0; nt < 4; ++nt) {
                const uint32_t* krow = KVs + (cb + nt * 8 + g) * KPITCH;
                uint32_t b0 = krow[kk + m];
                uint32_t b1 = krow[kk + m + 4];
                mma_tf32(acc[nt], qa[ks][0], qa[ks][1], qa[ks][2], qa[ks][3], b0, b1);
            }
        }

        // tile fully inside the window for every (r, c)?
        const bool full = (kt >= qs + BQ - 1 - WINDOW) && (kt + BK - 1 <= qs);
        const int rbase0 = qs + rw + g;        // query index of acc row block 0
        const int cbase  = kt + cb + 2 * m;    // kv index base for this thread

        // epilogue: scale, tanh-cap, mask, exp, store to E
#pragma unroll
        for (int nt = 0; nt < 4; ++nt) {
#pragma unroll
            for (int e = 0; e < 4; ++e) {
                int r = rw + g + ((e >> 1) << 3);
                int c = cb + nt * 8 + 2 * m + (e & 1);
                float y = acc[nt][e] * SCALE_Y;        // = tanh argument
                float capped;
                if (fabsf(y) < 0.25f) {
                    // tanh(y) ~ y*(1 + u*(-1/3 + u*(2/15 + u*(-17/315)))), u=y^2
                    float u = y * y;
                    float p = fmaf(u, -0.05396825397f, 0.13333333333f);
                    p = fmaf(u, p, -0.33333333333f);
                    p = fmaf(u, p, 1.0f);
                    capped = CAPV * y * p;
                } else {
                    float x = fminf(fmaxf(2.0f * y, -20.0f), 20.0f);
                    float e2x = __expf(x);
                    capped = CAPV * (e2x - 1.0f) * __frcp_rn(e2x + 1.0f);
                }
                float ev = __expf(capped);
                if (!full) {
                    int i = rbase0 + ((e >> 1) << 3);
                    int j = cbase + nt * 8 + (e & 1);
                    if (j < i - WINDOW || j > i) ev = 0.0f;
                }
                Es[r * EPITCH + t * BK + c] = ev;
            }
        }
    }

    // ---- prefetch V tile 0 (overlaps row-sum reduction) ----
    tile_ldg(pf, vbase, kstart, kv_row_stride, tid);

    __syncthreads();

    // ---- row sums -> Ls[r] = 1.02 / l ----
    {
        const int r = tid >> 2;       // 4 threads per row
        const int part = tid & 3;
        const int ncols = ntiles * BK;
        float s = 0.0f;
        const float* erow = Es + r * EPITCH;
        for (int c = part; c < ncols; c += 4) s += erow[c];
        s += __shfl_xor_sync(0xffffffff, s, 1);
        s += __shfl_xor_sync(0xffffffff, s, 2);
        if (part == 0) Ls[r] = 1.02f / s;
    }
    __syncthreads();

    // ================= PASS 2: O = clip(p) @ V =================
    const int rw2 = (warp & 3) * 16;
    const int cb2 = (warp >> 2) * 64;   // 8 n-tiles of 8 cols

    const float linv0 = Ls[rw2 + g];
    const float linv1 = Ls[rw2 + g + 8];

    float oacc[8][4];
#pragma unroll
    for (int nt = 0; nt < 8; ++nt)
#pragma unroll
        for (int e = 0; e < 4; ++e) oacc[nt][e] = 0.0f;

    for (int t = 0; t < ntiles; ++t) {
        const int kt = kstart + t * BK;
        __syncthreads();                 // prev tile's consumers done
        tile_sts(pf, KVs, VPITCH, tid);  // V tile t -> smem
        __syncthreads();
        if (t + 1 < ntiles)              // overlap tile t+1 LDG with MMA of t
            tile_ldg(pf, vbase, kt + BK, kv_row_stride, tid);

        const float* e0row = Es + (rw2 + g) * EPITCH + t * BK;
        const float* e1row = Es + (rw2 + g + 8) * EPITCH + t * BK;
#pragma unroll 2
        for (int ks = 0; ks < 8; ++ks) {
            const int kk = ks * 8;
            float p0 = fmaf(e0row[kk + m],     linv0, -0.01f);
            float p1 = fmaf(e1row[kk + m],     linv1, -0.01f);
            float p2 = fmaf(e0row[kk + m + 4], linv0, -0.01f);
            float p3 = fmaf(e1row[kk + m + 4], linv1, -0.01f);
            p0 = fminf(fmaxf(p0, 0.0f), 1.0f);
            p1 = fminf(fmaxf(p1, 0.0f), 1.0f);
            p2 = fminf(fmaxf(p2, 0.0f), 1.0f);
            p3 = fminf(fmaxf(p3, 0.0f), 1.0f);
            uint32_t a0 = f2tf32(p0);
            uint32_t a1 = f2tf32(p1);
            uint32_t a2 = f2tf32(p2);
            uint32_t a3 = f2tf32(p3);
#pragma unroll
            for (int nt = 0; nt < 8; ++nt) {
                const int dcol = cb2 + nt * 8 + g;
                uint32_t b0 = KVs[(kk + m) * VPITCH + dcol];
                uint32_t b1 = KVs[(kk + m + 4) * VPITCH + dcol];
                mma_tf32(oacc[nt], a0, a1, a2, a3, b0, b1);
            }
        }
    }

    // ---- store O ----
    float* obase = out + (((size_t)b * SQ + qs) * NUM_Q_HEAD + h) * HEAD_DIM;
#pragma unroll
    for (int nt = 0; nt < 8; ++nt) {
        const int col = cb2 + nt * 8 + 2 * m;
        float2 v01 = make_float2(oacc[nt][0], oacc[nt][1]);
        float2 v23 = make_float2(oacc[nt][2], oacc[nt][3]);
        *reinterpret_cast<float2*>(obase + (size_t)(rw2 + g) * q_row_stride + col) = v01;
        *reinterpret_cast<float2*>(obase + (size_t)(rw2 + g + 8) * q_row_stride + col) = v23;
    }
}

extern "C" void kernel_launch(void* const* d_in, const int* in_sizes, int n_in,
                              void* d_out, int out_size) {
    const float* q = (const float*)d_in[0];
    const float* k = (const float*)d_in[1];
    const float* v = (const float*)d_in[2];
    float* out = (float*)d_out;

    const int SQ = 2048;
    const int B = in_sizes[0] / (SQ * NUM_Q_HEAD * HEAD_DIM);

    cudaFuncSetAttribute(swa_kernel, cudaFuncAttributeMaxDynamicSharedMemorySize, SM_TOTAL);

    dim3 grid(SQ / BQ, NUM_Q_HEAD, B);
    swa_kernel<<<grid, NTHREADS, SM_TOTAL>>>(q, k, v, out, SQ);
}